// round 8
// baseline (speedup 1.0000x reference)
#include <cuda_runtime.h>
#include <math.h>

// Problem constants
#define BATCH 4
#define SEQ   1024
#define DIM   1024
#define NH    16
#define DH    64
#define MROWS (BATCH * SEQ)   // 4096

// Scratch buffers (allocation-free rule: __device__ globals)
__device__ float g_Q[MROWS * DIM];
__device__ float g_K[MROWS * DIM];
__device__ float g_V[MROWS * DIM];
__device__ float g_O[MROWS * DIM];

// ----------------------------------------------------------------------------
// Simple NT SGEMM with bias: C[m,n] = sum_k A[m,k]*B[n,k] + bias[n]
// 64x64 tiles, k-tiles of 16, 256 threads (16x16), 4x4 accumulators.
// ----------------------------------------------------------------------------
__global__ __launch_bounds__(256) void gemm64_nt_bias(
    const float* __restrict__ A, const float* __restrict__ B,
    const float* __restrict__ bias, float* __restrict__ C,
    int M, int N, int K)
{
    __shared__ float As[64][17];
    __shared__ float Bs[64][17];

    const int bm = blockIdx.y * 64;
    const int bn = blockIdx.x * 64;
    const int t  = threadIdx.x;
    const int tx = t & 15;
    const int ty = t >> 4;

    float acc[4][4];
#pragma unroll
    for (int i = 0; i < 4; i++)
#pragma unroll
        for (int j = 0; j < 4; j++) acc[i][j] = 0.0f;

    for (int k0 = 0; k0 < K; k0 += 16) {
        for (int u = t; u < 64 * 16; u += 256) {
            const int r = u >> 4;
            const int c = u & 15;
            As[r][c] = A[(size_t)(bm + r) * K + k0 + c];
            Bs[r][c] = B[(size_t)(bn + r) * K + k0 + c];
        }
        __syncthreads();

#pragma unroll
        for (int kk = 0; kk < 16; kk++) {
            float a[4], b[4];
#pragma unroll
            for (int i = 0; i < 4; i++) a[i] = As[ty * 4 + i][kk];
#pragma unroll
            for (int j = 0; j < 4; j++) b[j] = Bs[tx * 4 + j][kk];
#pragma unroll
            for (int i = 0; i < 4; i++)
#pragma unroll
                for (int j = 0; j < 4; j++)
                    acc[i][j] = fmaf(a[i], b[j], acc[i][j]);
        }
        __syncthreads();
    }

#pragma unroll
    for (int i = 0; i < 4; i++) {
        const int m = bm + ty * 4 + i;
#pragma unroll
        for (int j = 0; j < 4; j++) {
            const int n = bn + tx * 4 + j;
            C[(size_t)m * N + n] = acc[i][j] + bias[n];
        }
    }
}

// ----------------------------------------------------------------------------
// Attention with fused RoPE, REVERSE rotation (-sin), one WARP per (b,h,q).
// Lane j (0..31) owns the half-split dim pair (j, j+32):
//   rot[j]    = x[j]*cos(a_j)    + x[j+32]*sin(a_j)
//   rot[j+32] = x[j+32]*cos(a_j) - x[j]   *sin(a_j),  a_j = pos * theta^(-2j/64)
// Online softmax over all 1024 keys. V/O dims owned as (lane, lane+32).
// ----------------------------------------------------------------------------
__global__ __launch_bounds__(256) void attn_rope_negsin(
    const float* __restrict__ Q, const float* __restrict__ K,
    const float* __restrict__ V, float* __restrict__ O)
{
    const int warp = threadIdx.x >> 5;
    const int lane = threadIdx.x & 31;
    const int idx  = blockIdx.x * 8 + warp;       // ((b*NH + h)*SEQ + q)
    const int q    = idx & (SEQ - 1);
    const int h    = (idx >> 10) & (NH - 1);
    const int b    = idx >> 14;

    // Per-lane rope frequency for plane j = lane: theta^(-2*lane/64)
    const float inv_freq = expf(-((float)(2 * lane) / (float)DH) * logf(10000.0f));

    // Load + rotate (reverse) + scale query
    const size_t row_q = (size_t)(b * SEQ + q) * DIM + h * DH;
    float cq, sq;
    sincosf((float)q * inv_freq, &cq, &sq);
    sq = -sq;   // reverse rotation
    const float qa = Q[row_q + lane];
    const float qb = Q[row_q + lane + 32];
    const float q0 = (qa * cq - qb * sq) * 0.125f;   // 1/sqrt(64)
    const float q1 = (qb * cq + qa * sq) * 0.125f;

    float m = -INFINITY, l = 0.0f, o0 = 0.0f, o1 = 0.0f;

    const size_t head_off = (size_t)b * SEQ * DIM + h * DH;
    for (int k = 0; k < SEQ; k++) {
        const size_t row_k = head_off + (size_t)k * DIM;
        float ck, sk;
        sincosf((float)k * inv_freq, &ck, &sk);
        sk = -sk;   // reverse rotation
        const float ka = K[row_k + lane];
        const float kb = K[row_k + lane + 32];
        const float k0 = ka * ck - kb * sk;
        const float k1 = kb * ck + ka * sk;

        float d = q0 * k0 + q1 * k1;
#pragma unroll
        for (int o = 16; o >= 1; o >>= 1)
            d += __shfl_xor_sync(0xffffffffu, d, o);
        // every lane now holds the full logit
        const float mn   = fmaxf(m, d);
        const float corr = __expf(m - mn);
        const float p    = __expf(d - mn);
        m = mn;
        l = l * corr + p;
        o0 = o0 * corr + p * V[row_k + lane];
        o1 = o1 * corr + p * V[row_k + lane + 32];
    }

    const float inv = 1.0f / l;
    O[row_q + lane]      = o0 * inv;
    O[row_q + lane + 32] = o1 * inv;
}

// ----------------------------------------------------------------------------
// Launch — strict dict-order input mapping: x, Wq, bq, Wk, bk, Wv, bv, Wo, bo
// ----------------------------------------------------------------------------
extern "C" void kernel_launch(void* const* d_in, const int* in_sizes, int n_in,
                              void* d_out, int out_size)
{
    (void)in_sizes; (void)n_in; (void)out_size;
    const float* x  = (const float*)d_in[0];
    const float* Wq = (const float*)d_in[1];
    const float* bq = (const float*)d_in[2];
    const float* Wk = (const float*)d_in[3];
    const float* bk = (const float*)d_in[4];
    const float* Wv = (const float*)d_in[5];
    const float* bv = (const float*)d_in[6];
    const float* Wo = (const float*)d_in[7];
    const float* bo = (const float*)d_in[8];
    float* out = (float*)d_out;

    float *Q, *K, *V, *O;
    cudaGetSymbolAddress((void**)&Q, g_Q);
    cudaGetSymbolAddress((void**)&K, g_K);
    cudaGetSymbolAddress((void**)&V, g_V);
    cudaGetSymbolAddress((void**)&O, g_O);

    const dim3 ggrid(DIM / 64, MROWS / 64);   // (16, 64)
    gemm64_nt_bias<<<ggrid, 256>>>(x, Wq, bq, Q, MROWS, DIM, DIM);
    gemm64_nt_bias<<<ggrid, 256>>>(x, Wk, bk, K, MROWS, DIM, DIM);
    gemm64_nt_bias<<<ggrid, 256>>>(x, Wv, bv, V, MROWS, DIM, DIM);

    const int n_queries = BATCH * NH * SEQ;        // 65536
    attn_rope_negsin<<<n_queries / 8, 256>>>(Q, K, V, O);

    gemm64_nt_bias<<<ggrid, 256>>>(O, Wo, bo, out, MROWS, DIM, DIM);
}

// round 9
// speedup vs baseline: 4.5668x; 4.5668x over previous
#include <cuda_runtime.h>
#include <math.h>

// Problem constants
#define BATCH 4
#define SEQ   1024
#define DIM   1024
#define NH    16
#define DH    64
#define MROWS (BATCH * SEQ)   // 4096

// Scratch buffers (allocation-free rule: __device__ globals)
__device__ float g_Q[MROWS * DIM];
__device__ float g_K[MROWS * DIM];
__device__ float g_V[MROWS * DIM];
__device__ float g_O[MROWS * DIM];

// ----------------------------------------------------------------------------
// NT SGEMM with bias: C[m,n] = sum_k A[m,k] * B[n,k] + bias[n]
// A: [M,K] row-major, B: [N,K] row-major (both K-contiguous -> float4 loads)
// Tiles: 128x128x8, 256 threads, 8x8 per-thread register blocking (split 4+4).
// ----------------------------------------------------------------------------
__global__ __launch_bounds__(256, 2) void gemm_nt_bias(
    const float* __restrict__ A, const float* __restrict__ B,
    const float* __restrict__ bias, float* __restrict__ C,
    int M, int N, int K)
{
    __shared__ float As[8][128];
    __shared__ float Bs[8][128];

    const int bm = blockIdx.y * 128;
    const int bn = blockIdx.x * 128;
    const int t  = threadIdx.x;
    const int tx = t & 15;
    const int ty = t >> 4;

    const int lrow = t >> 1;          // 0..127
    const int lk   = (t & 1) * 4;     // 0 or 4
    const float* Aptr = A + (size_t)(bm + lrow) * K + lk;
    const float* Bptr = B + (size_t)(bn + lrow) * K + lk;

    float acc[8][8];
#pragma unroll
    for (int i = 0; i < 8; i++)
#pragma unroll
        for (int j = 0; j < 8; j++) acc[i][j] = 0.0f;

    for (int k0 = 0; k0 < K; k0 += 8) {
        const float4 va = *(const float4*)(Aptr + k0);
        const float4 vb = *(const float4*)(Bptr + k0);
        As[lk + 0][lrow] = va.x;
        As[lk + 1][lrow] = va.y;
        As[lk + 2][lrow] = va.z;
        As[lk + 3][lrow] = va.w;
        Bs[lk + 0][lrow] = vb.x;
        Bs[lk + 1][lrow] = vb.y;
        Bs[lk + 2][lrow] = vb.z;
        Bs[lk + 3][lrow] = vb.w;
        __syncthreads();

#pragma unroll
        for (int kk = 0; kk < 8; kk++) {
            float a[8], b[8];
            {
                const float4 a0 = *(const float4*)&As[kk][ty * 4];
                const float4 a1 = *(const float4*)&As[kk][64 + ty * 4];
                a[0] = a0.x; a[1] = a0.y; a[2] = a0.z; a[3] = a0.w;
                a[4] = a1.x; a[5] = a1.y; a[6] = a1.z; a[7] = a1.w;
                const float4 b0 = *(const float4*)&Bs[kk][tx * 4];
                const float4 b1 = *(const float4*)&Bs[kk][64 + tx * 4];
                b[0] = b0.x; b[1] = b0.y; b[2] = b0.z; b[3] = b0.w;
                b[4] = b1.x; b[5] = b1.y; b[6] = b1.z; b[7] = b1.w;
            }
#pragma unroll
            for (int i = 0; i < 8; i++)
#pragma unroll
                for (int j = 0; j < 8; j++)
                    acc[i][j] = fmaf(a[i], b[j], acc[i][j]);
        }
        __syncthreads();
    }

#pragma unroll
    for (int ih = 0; ih < 2; ih++) {
#pragma unroll
        for (int r = 0; r < 4; r++) {
            const int m = bm + ih * 64 + ty * 4 + r;
#pragma unroll
            for (int jh = 0; jh < 2; jh++) {
                const int n = bn + jh * 64 + tx * 4;
                const float4 bv = *(const float4*)&bias[n];
                float4 o;
                o.x = acc[ih * 4 + r][jh * 4 + 0] + bv.x;
                o.y = acc[ih * 4 + r][jh * 4 + 1] + bv.y;
                o.z = acc[ih * 4 + r][jh * 4 + 2] + bv.z;
                o.w = acc[ih * 4 + r][jh * 4 + 3] + bv.w;
                *(float4*)&C[(size_t)m * N + n] = o;
            }
        }
    }
}

// ----------------------------------------------------------------------------
// RoPE, REVERSE rotation (-sin), half-split pairs (j, j+32):
//   out[j]    = x[j]*cos(a)    + x[j+32]*sin(a)
//   out[j+32] = x[j+32]*cos(a) - x[j]   *sin(a),  a = s * theta^(-2j/64)
// One thread per (b,s,h,j), j in [0,32). In-place.
// ----------------------------------------------------------------------------
__global__ void rope_negsin_kernel(float* __restrict__ X)
{
    const int idx = blockIdx.x * blockDim.x + threadIdx.x;
    const int total = BATCH * SEQ * NH * 32;
    if (idx >= total) return;
    const int j    = idx & 31;
    const int rest = idx >> 5;            // ((b*SEQ + s)*NH + h)
    const int s    = (rest / NH) % SEQ;
    const size_t base = (size_t)rest * DH;

    const float inv_freq = expf(-((float)(2 * j) / (float)DH) * logf(10000.0f));
    const float ang = (float)s * inv_freq;
    float c, sn;
    sincosf(ang, &c, &sn);

    const float x1 = X[base + j];
    const float x2 = X[base + j + 32];
    X[base + j]      = x1 * c + x2 * sn;   // reverse rotation
    X[base + j + 32] = x2 * c - x1 * sn;
}

// ----------------------------------------------------------------------------
// Flash attention: per (b, h, 64-row q-tile). Online softmax over 32 kv tiles
// of 32 keys. STATIC shared memory (44.5KB < 48KB, no opt-in).
//   Qt[d][q]   64x68  - Q tile transposed, pre-scaled by 1/8
//   Kt[d][k]   64x36  - K tile transposed (32 keys)
//   Vs[k][d]   32x68  - V tile natural
//   Pq[q][k]   64x36  - probabilities
// Threads 16x16: S-stage thread owns q rows ty*4..+3, keys tx*2..+1;
// PV-stage owns q rows ty*4..+3, dims tx*4..+3.
// ----------------------------------------------------------------------------
__global__ __launch_bounds__(256) void flash_attn(
    const float* __restrict__ Q, const float* __restrict__ K,
    const float* __restrict__ V, float* __restrict__ O)
{
    __shared__ float Qt[64][68];
    __shared__ float Kt[64][36];
    __shared__ float Vs[32][68];
    __shared__ float Pq[64][36];

    const int qt = blockIdx.x;   // 0..15
    const int h  = blockIdx.y;   // 0..15
    const int b  = blockIdx.z;   // 0..3
    const int t  = threadIdx.x;
    const int tx = t & 15;
    const int ty = t >> 4;

    const int base_col = h * DH;
    const int q0 = qt * 64;
    const float scale = 0.125f;   // 1/sqrt(64)

    // Load Q tile transposed + pre-scaled
    for (int u = t; u < 64 * 16; u += 256) {
        const int row = u >> 4;
        const int c   = (u & 15) * 4;
        const float4 v = *(const float4*)&Q[((size_t)(b * SEQ + q0 + row)) * DIM + base_col + c];
        Qt[c + 0][row] = v.x * scale;
        Qt[c + 1][row] = v.y * scale;
        Qt[c + 2][row] = v.z * scale;
        Qt[c + 3][row] = v.w * scale;
    }

    float m_i[4], l_i[4], acc[4][4];
#pragma unroll
    for (int i = 0; i < 4; i++) {
        m_i[i] = -1e30f;
        l_i[i] = 0.0f;
#pragma unroll
        for (int j = 0; j < 4; j++) acc[i][j] = 0.0f;
    }

    for (int kt = 0; kt < SEQ; kt += 32) {
        __syncthreads();   // prev-iter consumers done with Kt/Vs/Pq (covers Q load 1st iter)
        for (int u = t; u < 32 * 16; u += 256) {
            const int row = u >> 4;          // 0..31 key in tile
            const int c   = (u & 15) * 4;    // dim
            const size_t g = ((size_t)(b * SEQ + kt + row)) * DIM + base_col + c;
            const float4 kv = *(const float4*)&K[g];
            Kt[c + 0][row] = kv.x;
            Kt[c + 1][row] = kv.y;
            Kt[c + 2][row] = kv.z;
            Kt[c + 3][row] = kv.w;
            *(float4*)&Vs[row][c] = *(const float4*)&V[g];
        }
        __syncthreads();

        // S = (Q*scale) K^T : 4 q-rows x 2 keys per thread
        float s00 = 0.f, s01 = 0.f, s10 = 0.f, s11 = 0.f;
        float s20 = 0.f, s21 = 0.f, s30 = 0.f, s31 = 0.f;
#pragma unroll 16
        for (int d = 0; d < 64; d++) {
            const float4 qa = *(const float4*)&Qt[d][ty * 4];
            const float2 kb = *(const float2*)&Kt[d][tx * 2];
            s00 = fmaf(qa.x, kb.x, s00); s01 = fmaf(qa.x, kb.y, s01);
            s10 = fmaf(qa.y, kb.x, s10); s11 = fmaf(qa.y, kb.y, s11);
            s20 = fmaf(qa.z, kb.x, s20); s21 = fmaf(qa.z, kb.y, s21);
            s30 = fmaf(qa.w, kb.x, s30); s31 = fmaf(qa.w, kb.y, s31);
        }
        float sv[4][2] = {{s00, s01}, {s10, s11}, {s20, s21}, {s30, s31}};

        // Online softmax update (row stats replicated across 16-lane group)
#pragma unroll
        for (int i = 0; i < 4; i++) {
            float mx = fmaxf(sv[i][0], sv[i][1]);
#pragma unroll
            for (int o = 1; o < 16; o <<= 1)
                mx = fmaxf(mx, __shfl_xor_sync(0xffffffffu, mx, o));
            const float mn = fmaxf(m_i[i], mx);
            const float corr = __expf(m_i[i] - mn);
            m_i[i] = mn;
            const float p0 = __expf(sv[i][0] - mn);
            const float p1 = __expf(sv[i][1] - mn);
            float ps = p0 + p1;
#pragma unroll
            for (int o = 1; o < 16; o <<= 1)
                ps += __shfl_xor_sync(0xffffffffu, ps, o);
            l_i[i] = l_i[i] * corr + ps;
#pragma unroll
            for (int j = 0; j < 4; j++) acc[i][j] *= corr;
            sv[i][0] = p0;
            sv[i][1] = p1;
        }

        // Write P tile
#pragma unroll
        for (int i = 0; i < 4; i++) {
            float2 p2;
            p2.x = sv[i][0];
            p2.y = sv[i][1];
            *(float2*)&Pq[ty * 4 + i][tx * 2] = p2;
        }
        __syncthreads();

        // O += P V
#pragma unroll 8
        for (int k = 0; k < 32; k++) {
            const float a0 = Pq[ty * 4 + 0][k];
            const float a1 = Pq[ty * 4 + 1][k];
            const float a2 = Pq[ty * 4 + 2][k];
            const float a3 = Pq[ty * 4 + 3][k];
            const float4 v4 = *(const float4*)&Vs[k][tx * 4];
            acc[0][0] = fmaf(a0, v4.x, acc[0][0]);
            acc[0][1] = fmaf(a0, v4.y, acc[0][1]);
            acc[0][2] = fmaf(a0, v4.z, acc[0][2]);
            acc[0][3] = fmaf(a0, v4.w, acc[0][3]);
            acc[1][0] = fmaf(a1, v4.x, acc[1][0]);
            acc[1][1] = fmaf(a1, v4.y, acc[1][1]);
            acc[1][2] = fmaf(a1, v4.z, acc[1][2]);
            acc[1][3] = fmaf(a1, v4.w, acc[1][3]);
            acc[2][0] = fmaf(a2, v4.x, acc[2][0]);
            acc[2][1] = fmaf(a2, v4.y, acc[2][1]);
            acc[2][2] = fmaf(a2, v4.z, acc[2][2]);
            acc[2][3] = fmaf(a2, v4.w, acc[2][3]);
            acc[3][0] = fmaf(a3, v4.x, acc[3][0]);
            acc[3][1] = fmaf(a3, v4.y, acc[3][1]);
            acc[3][2] = fmaf(a3, v4.z, acc[3][2]);
            acc[3][3] = fmaf(a3, v4.w, acc[3][3]);
        }
    }

    // Normalize and write O
#pragma unroll
    for (int i = 0; i < 4; i++) {
        const float inv = 1.0f / l_i[i];
        float4 o;
        o.x = acc[i][0] * inv;
        o.y = acc[i][1] * inv;
        o.z = acc[i][2] * inv;
        o.w = acc[i][3] * inv;
        *(float4*)&O[((size_t)(b * SEQ + q0 + ty * 4 + i)) * DIM + base_col + tx * 4] = o;
    }
}

// ----------------------------------------------------------------------------
// Launch — strict dict-order input mapping: x, Wq, bq, Wk, bk, Wv, bv, Wo, bo
// ----------------------------------------------------------------------------
extern "C" void kernel_launch(void* const* d_in, const int* in_sizes, int n_in,
                              void* d_out, int out_size)
{
    (void)in_sizes; (void)n_in; (void)out_size;
    const float* x  = (const float*)d_in[0];
    const float* Wq = (const float*)d_in[1];
    const float* bq = (const float*)d_in[2];
    const float* Wk = (const float*)d_in[3];
    const float* bk = (const float*)d_in[4];
    const float* Wv = (const float*)d_in[5];
    const float* bv = (const float*)d_in[6];
    const float* Wo = (const float*)d_in[7];
    const float* bo = (const float*)d_in[8];
    float* out = (float*)d_out;

    float *Q, *K, *V, *O;
    cudaGetSymbolAddress((void**)&Q, g_Q);
    cudaGetSymbolAddress((void**)&K, g_K);
    cudaGetSymbolAddress((void**)&V, g_V);
    cudaGetSymbolAddress((void**)&O, g_O);

    const dim3 ggrid(DIM / 128, MROWS / 128);   // (8, 32)
    gemm_nt_bias<<<ggrid, 256>>>(x, Wq, bq, Q, MROWS, DIM, DIM);
    gemm_nt_bias<<<ggrid, 256>>>(x, Wk, bk, K, MROWS, DIM, DIM);
    gemm_nt_bias<<<ggrid, 256>>>(x, Wv, bv, V, MROWS, DIM, DIM);

    const int rope_threads = BATCH * SEQ * NH * 32;
    const int rope_blocks = (rope_threads + 255) / 256;
    rope_negsin_kernel<<<rope_blocks, 256>>>(Q);
    rope_negsin_kernel<<<rope_blocks, 256>>>(K);

    const dim3 agrid(SEQ / 64, NH, BATCH);      // (16, 16, 4)
    flash_attn<<<agrid, 256>>>(Q, K, V, O);

    gemm_nt_bias<<<ggrid, 256>>>(O, Wo, bo, out, MROWS, DIM, DIM);
}

// round 10
// speedup vs baseline: 6.7966x; 1.4883x over previous
#include <cuda_runtime.h>
#include <math.h>
#include <stdint.h>

// Problem constants
#define BATCH 4
#define SEQ   1024
#define DIM   1024
#define NH    16
#define DH    64
#define MROWS (BATCH * SEQ)   // 4096

// Scratch buffers (allocation-free rule: __device__ globals)
__device__ float g_Q[MROWS * DIM];
__device__ float g_K[MROWS * DIM];
__device__ float g_V[MROWS * DIM];
__device__ float g_O[MROWS * DIM];

// ----------------------------------------------------------------------------
// TF32 tensor-core NT GEMM with bias: C[m,n] = sum_k A[m,k]*B[n,k] + bias[n]
// mma.sync.m16n8k8 tf32 (fallback HMMA on sm_103a).
// Tile: 128x128x16. 8 warps, warp tile 64m x 32n = 4x4 mma tiles.
// Smem: [row][k] natural layout, stride 20 words (conflict-free for frag loads).
// fp32 accumulate, fp32 bias epilogue. Inputs rounded via cvt.rna.tf32.
// ----------------------------------------------------------------------------
__device__ __forceinline__ uint32_t f32_to_tf32(float f) {
    uint32_t u;
    asm("cvt.rna.tf32.f32 %0, %1;" : "=r"(u) : "f"(f));
    return u;
}

__global__ __launch_bounds__(256, 2) void gemm_tf32_nt_bias(
    const float* __restrict__ A, const float* __restrict__ B,
    const float* __restrict__ bias, float* __restrict__ C,
    int M, int N, int K)
{
    __shared__ uint32_t As[128][20];
    __shared__ uint32_t Bs[128][20];

    const int bm   = blockIdx.y * 128;
    const int bn   = blockIdx.x * 128;
    const int t    = threadIdx.x;
    const int warp = t >> 5;
    const int lane = t & 31;
    const int wm   = (warp & 1) * 64;    // warp m-offset: 0 / 64
    const int wn   = (warp >> 1) * 32;   // warp n-offset: 0 / 32 / 64 / 96

    // Gmem loader mapping: thread covers row (t>>1), k-cols (t&1)*8 .. +7
    const int lrow = t >> 1;
    const int lk   = (t & 1) * 8;
    const float* Ap = A + (size_t)(bm + lrow) * K + lk;
    const float* Bp = B + (size_t)(bn + lrow) * K + lk;

    float acc[4][4][4];   // [mt][nt][c0..c3]
#pragma unroll
    for (int mt = 0; mt < 4; mt++)
#pragma unroll
        for (int nt = 0; nt < 4; nt++)
#pragma unroll
            for (int c = 0; c < 4; c++) acc[mt][nt][c] = 0.0f;

    // Prefetch first k-tile into registers
    float4 ra0 = *(const float4*)(Ap);
    float4 ra1 = *(const float4*)(Ap + 4);
    float4 rb0 = *(const float4*)(Bp);
    float4 rb1 = *(const float4*)(Bp + 4);

    for (int k0 = 0; k0 < K; k0 += 16) {
        // Stage current tile (converted to tf32 bits)
        As[lrow][lk + 0] = f32_to_tf32(ra0.x);
        As[lrow][lk + 1] = f32_to_tf32(ra0.y);
        As[lrow][lk + 2] = f32_to_tf32(ra0.z);
        As[lrow][lk + 3] = f32_to_tf32(ra0.w);
        As[lrow][lk + 4] = f32_to_tf32(ra1.x);
        As[lrow][lk + 5] = f32_to_tf32(ra1.y);
        As[lrow][lk + 6] = f32_to_tf32(ra1.z);
        As[lrow][lk + 7] = f32_to_tf32(ra1.w);
        Bs[lrow][lk + 0] = f32_to_tf32(rb0.x);
        Bs[lrow][lk + 1] = f32_to_tf32(rb0.y);
        Bs[lrow][lk + 2] = f32_to_tf32(rb0.z);
        Bs[lrow][lk + 3] = f32_to_tf32(rb0.w);
        Bs[lrow][lk + 4] = f32_to_tf32(rb1.x);
        Bs[lrow][lk + 5] = f32_to_tf32(rb1.y);
        Bs[lrow][lk + 6] = f32_to_tf32(rb1.z);
        Bs[lrow][lk + 7] = f32_to_tf32(rb1.w);
        __syncthreads();

        // Prefetch next tile while computing
        if (k0 + 16 < K) {
            ra0 = *(const float4*)(Ap + k0 + 16);
            ra1 = *(const float4*)(Ap + k0 + 20);
            rb0 = *(const float4*)(Bp + k0 + 16);
            rb1 = *(const float4*)(Bp + k0 + 20);
        }

#pragma unroll
        for (int ks = 0; ks < 2; ks++) {
            const int kb = ks * 8;
            const int gr = lane >> 2;    // group row 0..7
            const int gc = lane & 3;     // in-group col 0..3

            uint32_t af[4][4];
#pragma unroll
            for (int mt = 0; mt < 4; mt++) {
                const int r = wm + mt * 16 + gr;
                af[mt][0] = As[r][kb + gc];
                af[mt][1] = As[r + 8][kb + gc];
                af[mt][2] = As[r][kb + gc + 4];
                af[mt][3] = As[r + 8][kb + gc + 4];
            }
            uint32_t bf[4][2];
#pragma unroll
            for (int nt = 0; nt < 4; nt++) {
                const int r = wn + nt * 8 + gr;
                bf[nt][0] = Bs[r][kb + gc];
                bf[nt][1] = Bs[r][kb + gc + 4];
            }
#pragma unroll
            for (int mt = 0; mt < 4; mt++)
#pragma unroll
                for (int nt = 0; nt < 4; nt++) {
                    asm volatile(
                        "mma.sync.aligned.m16n8k8.row.col.f32.tf32.tf32.f32 "
                        "{%0,%1,%2,%3}, {%4,%5,%6,%7}, {%8,%9}, {%0,%1,%2,%3};"
                        : "+f"(acc[mt][nt][0]), "+f"(acc[mt][nt][1]),
                          "+f"(acc[mt][nt][2]), "+f"(acc[mt][nt][3])
                        : "r"(af[mt][0]), "r"(af[mt][1]), "r"(af[mt][2]), "r"(af[mt][3]),
                          "r"(bf[nt][0]), "r"(bf[nt][1]));
                }
        }
        __syncthreads();
    }

    // Epilogue: bias add + store (c0,c1 at row; c2,c3 at row+8)
    const int gr = lane >> 2;
    const int gc = lane & 3;
#pragma unroll
    for (int mt = 0; mt < 4; mt++) {
        const int m0 = bm + wm + mt * 16 + gr;
#pragma unroll
        for (int nt = 0; nt < 4; nt++) {
            const int n0 = bn + wn + nt * 8 + gc * 2;
            const float b0v = bias[n0];
            const float b1v = bias[n0 + 1];
            float2 v01;
            v01.x = acc[mt][nt][0] + b0v;
            v01.y = acc[mt][nt][1] + b1v;
            *(float2*)&C[(size_t)m0 * N + n0] = v01;
            float2 v23;
            v23.x = acc[mt][nt][2] + b0v;
            v23.y = acc[mt][nt][3] + b1v;
            *(float2*)&C[(size_t)(m0 + 8) * N + n0] = v23;
        }
    }
}

// ----------------------------------------------------------------------------
// RoPE, REVERSE rotation (-sin), half-split pairs (j, j+32):
//   out[j]    = x[j]*cos(a)    + x[j+32]*sin(a)
//   out[j+32] = x[j+32]*cos(a) - x[j]   *sin(a),  a = s * theta^(-2j/64)
// ----------------------------------------------------------------------------
__global__ void rope_negsin_kernel(float* __restrict__ X)
{
    const int idx = blockIdx.x * blockDim.x + threadIdx.x;
    const int total = BATCH * SEQ * NH * 32;
    if (idx >= total) return;
    const int j    = idx & 31;
    const int rest = idx >> 5;            // ((b*SEQ + s)*NH + h)
    const int s    = (rest / NH) % SEQ;
    const size_t base = (size_t)rest * DH;

    const float inv_freq = expf(-((float)(2 * j) / (float)DH) * logf(10000.0f));
    const float ang = (float)s * inv_freq;
    float c, sn;
    sincosf(ang, &c, &sn);

    const float x1 = X[base + j];
    const float x2 = X[base + j + 32];
    X[base + j]      = x1 * c + x2 * sn;   // reverse rotation
    X[base + j + 32] = x2 * c - x1 * sn;
}

// ----------------------------------------------------------------------------
// Flash attention (fp32 SIMT): per (b, h, 64-row q-tile), 32-key tiles,
// static smem 44.5KB. Unchanged from R9 (known-good).
// ----------------------------------------------------------------------------
__global__ __launch_bounds__(256) void flash_attn(
    const float* __restrict__ Q, const float* __restrict__ K,
    const float* __restrict__ V, float* __restrict__ O)
{
    __shared__ float Qt[64][68];
    __shared__ float Kt[64][36];
    __shared__ float Vs[32][68];
    __shared__ float Pq[64][36];

    const int qt = blockIdx.x;
    const int h  = blockIdx.y;
    const int b  = blockIdx.z;
    const int t  = threadIdx.x;
    const int tx = t & 15;
    const int ty = t >> 4;

    const int base_col = h * DH;
    const int q0 = qt * 64;
    const float scale = 0.125f;

    for (int u = t; u < 64 * 16; u += 256) {
        const int row = u >> 4;
        const int c   = (u & 15) * 4;
        const float4 v = *(const float4*)&Q[((size_t)(b * SEQ + q0 + row)) * DIM + base_col + c];
        Qt[c + 0][row] = v.x * scale;
        Qt[c + 1][row] = v.y * scale;
        Qt[c + 2][row] = v.z * scale;
        Qt[c + 3][row] = v.w * scale;
    }

    float m_i[4], l_i[4], acc[4][4];
#pragma unroll
    for (int i = 0; i < 4; i++) {
        m_i[i] = -1e30f;
        l_i[i] = 0.0f;
#pragma unroll
        for (int j = 0; j < 4; j++) acc[i][j] = 0.0f;
    }

    for (int kt = 0; kt < SEQ; kt += 32) {
        __syncthreads();
        for (int u = t; u < 32 * 16; u += 256) {
            const int row = u >> 4;
            const int c   = (u & 15) * 4;
            const size_t g = ((size_t)(b * SEQ + kt + row)) * DIM + base_col + c;
            const float4 kv = *(const float4*)&K[g];
            Kt[c + 0][row] = kv.x;
            Kt[c + 1][row] = kv.y;
            Kt[c + 2][row] = kv.z;
            Kt[c + 3][row] = kv.w;
            *(float4*)&Vs[row][c] = *(const float4*)&V[g];
        }
        __syncthreads();

        float s00 = 0.f, s01 = 0.f, s10 = 0.f, s11 = 0.f;
        float s20 = 0.f, s21 = 0.f, s30 = 0.f, s31 = 0.f;
#pragma unroll 16
        for (int d = 0; d < 64; d++) {
            const float4 qa = *(const float4*)&Qt[d][ty * 4];
            const float2 kb = *(const float2*)&Kt[d][tx * 2];
            s00 = fmaf(qa.x, kb.x, s00); s01 = fmaf(qa.x, kb.y, s01);
            s10 = fmaf(qa.y, kb.x, s10); s11 = fmaf(qa.y, kb.y, s11);
            s20 = fmaf(qa.z, kb.x, s20); s21 = fmaf(qa.z, kb.y, s21);
            s30 = fmaf(qa.w, kb.x, s30); s31 = fmaf(qa.w, kb.y, s31);
        }
        float sv[4][2] = {{s00, s01}, {s10, s11}, {s20, s21}, {s30, s31}};

#pragma unroll
        for (int i = 0; i < 4; i++) {
            float mx = fmaxf(sv[i][0], sv[i][1]);
#pragma unroll
            for (int o = 1; o < 16; o <<= 1)
                mx = fmaxf(mx, __shfl_xor_sync(0xffffffffu, mx, o));
            const float mn = fmaxf(m_i[i], mx);
            const float corr = __expf(m_i[i] - mn);
            m_i[i] = mn;
            const float p0 = __expf(sv[i][0] - mn);
            const float p1 = __expf(sv[i][1] - mn);
            float ps = p0 + p1;
#pragma unroll
            for (int o = 1; o < 16; o <<= 1)
                ps += __shfl_xor_sync(0xffffffffu, ps, o);
            l_i[i] = l_i[i] * corr + ps;
#pragma unroll
            for (int j = 0; j < 4; j++) acc[i][j] *= corr;
            sv[i][0] = p0;
            sv[i][1] = p1;
        }

#pragma unroll
        for (int i = 0; i < 4; i++) {
            float2 p2;
            p2.x = sv[i][0];
            p2.y = sv[i][1];
            *(float2*)&Pq[ty * 4 + i][tx * 2] = p2;
        }
        __syncthreads();

#pragma unroll 8
        for (int k = 0; k < 32; k++) {
            const float a0 = Pq[ty * 4 + 0][k];
            const float a1 = Pq[ty * 4 + 1][k];
            const float a2 = Pq[ty * 4 + 2][k];
            const float a3 = Pq[ty * 4 + 3][k];
            const float4 v4 = *(const float4*)&Vs[k][tx * 4];
            acc[0][0] = fmaf(a0, v4.x, acc[0][0]);
            acc[0][1] = fmaf(a0, v4.y, acc[0][1]);
            acc[0][2] = fmaf(a0, v4.z, acc[0][2]);
            acc[0][3] = fmaf(a0, v4.w, acc[0][3]);
            acc[1][0] = fmaf(a1, v4.x, acc[1][0]);
            acc[1][1] = fmaf(a1, v4.y, acc[1][1]);
            acc[1][2] = fmaf(a1, v4.z, acc[1][2]);
            acc[1][3] = fmaf(a1, v4.w, acc[1][3]);
            acc[2][0] = fmaf(a2, v4.x, acc[2][0]);
            acc[2][1] = fmaf(a2, v4.y, acc[2][1]);
            acc[2][2] = fmaf(a2, v4.z, acc[2][2]);
            acc[2][3] = fmaf(a2, v4.w, acc[2][3]);
            acc[3][0] = fmaf(a3, v4.x, acc[3][0]);
            acc[3][1] = fmaf(a3, v4.y, acc[3][1]);
            acc[3][2] = fmaf(a3, v4.z, acc[3][2]);
            acc[3][3] = fmaf(a3, v4.w, acc[3][3]);
        }
    }

#pragma unroll
    for (int i = 0; i < 4; i++) {
        const float inv = 1.0f / l_i[i];
        float4 o;
        o.x = acc[i][0] * inv;
        o.y = acc[i][1] * inv;
        o.z = acc[i][2] * inv;
        o.w = acc[i][3] * inv;
        *(float4*)&O[((size_t)(b * SEQ + q0 + ty * 4 + i)) * DIM + base_col + tx * 4] = o;
    }
}

// ----------------------------------------------------------------------------
// Launch — strict dict-order input mapping: x, Wq, bq, Wk, bk, Wv, bv, Wo, bo
// ----------------------------------------------------------------------------
extern "C" void kernel_launch(void* const* d_in, const int* in_sizes, int n_in,
                              void* d_out, int out_size)
{
    (void)in_sizes; (void)n_in; (void)out_size;
    const float* x  = (const float*)d_in[0];
    const float* Wq = (const float*)d_in[1];
    const float* bq = (const float*)d_in[2];
    const float* Wk = (const float*)d_in[3];
    const float* bk = (const float*)d_in[4];
    const float* Wv = (const float*)d_in[5];
    const float* bv = (const float*)d_in[6];
    const float* Wo = (const float*)d_in[7];
    const float* bo = (const float*)d_in[8];
    float* out = (float*)d_out;

    float *Q, *K, *V, *O;
    cudaGetSymbolAddress((void**)&Q, g_Q);
    cudaGetSymbolAddress((void**)&K, g_K);
    cudaGetSymbolAddress((void**)&V, g_V);
    cudaGetSymbolAddress((void**)&O, g_O);

    const dim3 ggrid(DIM / 128, MROWS / 128);   // (8, 32)
    gemm_tf32_nt_bias<<<ggrid, 256>>>(x, Wq, bq, Q, MROWS, DIM, DIM);
    gemm_tf32_nt_bias<<<ggrid, 256>>>(x, Wk, bk, K, MROWS, DIM, DIM);
    gemm_tf32_nt_bias<<<ggrid, 256>>>(x, Wv, bv, V, MROWS, DIM, DIM);

    const int rope_threads = BATCH * SEQ * NH * 32;
    const int rope_blocks = (rope_threads + 255) / 256;
    rope_negsin_kernel<<<rope_blocks, 256>>>(Q);
    rope_negsin_kernel<<<rope_blocks, 256>>>(K);

    const dim3 agrid(SEQ / 64, NH, BATCH);      // (16, 16, 4)
    flash_attn<<<agrid, 256>>>(Q, K, V, O);

    gemm_tf32_nt_bias<<<ggrid, 256>>>(O, Wo, bo, out, MROWS, DIM, DIM);
}